// round 1
// baseline (speedup 1.0000x reference)
#include <cuda_runtime.h>

#define DINL __device__ __forceinline__

constexpr int N_NODES = 50000;
constexpr int N_EDGES = 1600000;
constexpr int NL = 5;
constexpr int NG = 4;
constexpr float EPS = 1e-5f;

// scratch (static device memory — no allocation in kernel_launch)
__device__ float g_h  [N_NODES * 64];
__device__ float g_hd [N_NODES * 64];
__device__ float g_hs [N_NODES * 64];
__device__ float g_agg[N_NODES * 64];
__device__ float g_pool[NG * 64];

typedef unsigned long long u64;

DINL u64 pk2(float x, float y) { u64 r; asm("mov.b64 %0,{%1,%2};" : "=l"(r) : "f"(x), "f"(y)); return r; }
DINL u64 dup2(float x) { return pk2(x, x); }
DINL float2 upk(u64 v) { float2 r; asm("mov.b64 {%0,%1},%2;" : "=f"(r.x), "=f"(r.y) : "l"(v)); return r; }
DINL u64 f2u(float2 v) { return pk2(v.x, v.y); }
DINL u64 ffma2(u64 a, u64 b, u64 c) {
    u64 d; asm("fma.rn.f32x2 %0,%1,%2,%3;" : "=l"(d) : "l"(a), "l"(b), "l"(c)); return d;
}
DINL void red2(float* p, float x, float y) {
    asm volatile("red.global.add.v2.f32 [%0], {%1,%2};" :: "l"(p), "f"(x), "f"(y) : "memory");
}
DINL float silu(float x) { return x / (1.f + __expf(-x)); }

// ---------------- encoder: h = LN(silu([x, gv[batch]] @ W1 + b1) @ W2 + b2) ----------------
__global__ void __launch_bounds__(256) k_encoder(
    const float* __restrict__ x, const int* __restrict__ batch,
    const float* __restrict__ casep, const float* __restrict__ bcp,
    const float* __restrict__ W1, const float* __restrict__ b1,
    const float* __restrict__ W2, const float* __restrict__ b2,
    const float* __restrict__ gam, const float* __restrict__ bet)
{
    __shared__ float sW1[16 * 64], sW2[64 * 64], sb1[64], sb2[64], sg[64], sbe[64];
    __shared__ float sH[8][64];
    int tid = threadIdx.x;
    for (int i = tid; i < 16 * 64; i += 256) sW1[i] = W1[i];
    for (int i = tid; i < 64 * 64; i += 256) sW2[i] = W2[i];
    if (tid < 64) { sb1[tid] = b1[tid]; sb2[tid] = b2[tid]; sg[tid] = gam[tid]; sbe[tid] = bet[tid]; }
    __syncthreads();
    int w = tid >> 5, ld = tid & 31, c0 = 2 * ld;
    int n = blockIdx.x * 8 + w;
    if (n >= N_NODES) return;
    float in[16];
#pragma unroll
    for (int k = 0; k < 8; k++) in[k] = __ldg(&x[n * 8 + k]);
    int g = __ldg(&batch[n]);
#pragma unroll
    for (int k = 0; k < 4; k++) { in[8 + k] = __ldg(&casep[g * 4 + k]); in[12 + k] = __ldg(&bcp[g * 4 + k]); }
    const float2* W1f = (const float2*)sW1;
    u64 acc = pk2(sb1[c0], sb1[c0 + 1]);
#pragma unroll
    for (int k = 0; k < 16; k++) acc = ffma2(dup2(in[k]), f2u(W1f[k * 32 + ld]), acc);
    float2 a = upk(acc);
    a.x = silu(a.x); a.y = silu(a.y);
    sH[w][c0] = a.x; sH[w][c0 + 1] = a.y;
    __syncwarp();
    const float2* W2f = (const float2*)sW2;
    u64 acc2 = pk2(sb2[c0], sb2[c0 + 1]);
#pragma unroll
    for (int k = 0; k < 64; k++) acc2 = ffma2(dup2(sH[w][k]), f2u(W2f[k * 32 + ld]), acc2);
    float2 v = upk(acc2);
    float s = v.x + v.y, q = v.x * v.x + v.y * v.y;
#pragma unroll
    for (int o = 16; o; o >>= 1) { s += __shfl_xor_sync(~0u, s, o); q += __shfl_xor_sync(~0u, q, o); }
    float m = s * (1.f / 64.f), var = q * (1.f / 64.f) - m * m, rs = rsqrtf(var + EPS);
    float2 out;
    out.x = (v.x - m) * rs * sg[c0] + sbe[c0];
    out.y = (v.y - m) * rs * sg[c0 + 1] + sbe[c0 + 1];
    *(float2*)(g_h + (size_t)n * 64 + c0) = out;
}

// ---------------- per-layer node pre-GEMMs: Hd = h@W1[0:64], Hs = h@W1[64:128]; also zeroes agg ----------------
__global__ void __launch_bounds__(256) k_node_pre(const float* __restrict__ eW1l)
{
    __shared__ float sA[64 * 64], sB[64 * 64];
    __shared__ float sRow[8][64];
    int tid = threadIdx.x;
    for (int i = tid; i < 4096; i += 256) { sA[i] = eW1l[i]; sB[i] = eW1l[4096 + i]; }
    __syncthreads();
    int w = tid >> 5, ld = tid & 31, c0 = 2 * ld;
    int n = blockIdx.x * 8 + w;
    if (n >= N_NODES) return;
    float2 hv = *(const float2*)(g_h + (size_t)n * 64 + c0);
    sRow[w][c0] = hv.x; sRow[w][c0 + 1] = hv.y;
    __syncwarp();
    const float2* Af = (const float2*)sA;
    const float2* Bf = (const float2*)sB;
    u64 ad = dup2(0.f), as_ = dup2(0.f);
#pragma unroll
    for (int k = 0; k < 64; k++) {
        u64 h = dup2(sRow[w][k]);
        ad  = ffma2(h, f2u(Af[k * 32 + ld]), ad);
        as_ = ffma2(h, f2u(Bf[k * 32 + ld]), as_);
    }
    *(float2*)(g_hd + (size_t)n * 64 + c0) = upk(ad);
    *(float2*)(g_hs + (size_t)n * 64 + c0) = upk(as_);
    *(float2*)(g_agg + (size_t)n * 64 + c0) = make_float2(0.f, 0.f);
}

// ---------------- edge kernel: warp handles 4 edges; m1 = Hd[dst]+Hs[src]+ea@W1c+b1; LN(silu(m1)@W2+b2); red into agg[dst] ----------------
__global__ void __launch_bounds__(256) k_edge(
    const int* __restrict__ ei, const float* __restrict__ eattr,
    const float* __restrict__ W1c, const float* __restrict__ b1,
    const float* __restrict__ W2, const float* __restrict__ b2,
    const float* __restrict__ gam, const float* __restrict__ bet)
{
    __shared__ float sW2[64 * 64], sW1c[5 * 64], sb1[64], sb2[64], sg[64], sbe[64];
    __shared__ float sM[8 * 256];   // per-warp [64 k][4 edges]
    int tid = threadIdx.x;
    for (int i = tid; i < 4096; i += 256) sW2[i] = W2[i];
    for (int i = tid; i < 320; i += 256) sW1c[i] = W1c[i];
    if (tid < 64) { sb1[tid] = b1[tid]; sb2[tid] = b2[tid]; sg[tid] = gam[tid]; sbe[tid] = bet[tid]; }
    __syncthreads();
    int w = tid >> 5, ld = tid & 31, c0 = 2 * ld;
    int wofs = w * 256;
    const float2* W2f = (const float2*)sW2;
    const float2* W1cf = (const float2*)sW1c;
    float2 b1v = ((const float2*)sb1)[ld];
    float2 b2v = ((const float2*)sb2)[ld];
    float2 gv  = ((const float2*)sg)[ld];
    float2 bev = ((const float2*)sbe)[ld];
    int gw = (blockIdx.x * 256 + tid) >> 5;
    int nw = (gridDim.x * 256) >> 5;
    for (int grp = gw; grp < N_EDGES / 4; grp += nw) {
        int e0 = grp * 4;
        int d[4];
        float2 mm[4];
#pragma unroll
        for (int i = 0; i < 4; i++) {
            int e = e0 + i;
            int s = __ldg(&ei[e]);
            d[i] = __ldg(&ei[N_EDGES + e]);
            float2 hd = *(const float2*)(g_hd + (size_t)d[i] * 64 + c0);
            float2 hs = *(const float2*)(g_hs + (size_t)s * 64 + c0);
            float2 m; m.x = hd.x + hs.x + b1v.x; m.y = hd.y + hs.y + b1v.y;
#pragma unroll
            for (int k = 0; k < 5; k++) {
                float a = __ldg(&eattr[(size_t)e * 5 + k]);
                float2 wv = W1cf[k * 32 + ld];
                m.x += a * wv.x; m.y += a * wv.y;
            }
            m.x = silu(m.x); m.y = silu(m.y);
            mm[i] = m;
        }
        __syncwarp();   // WAR vs previous iteration's reads
        *(float4*)&sM[wofs + 8 * ld]     = make_float4(mm[0].x, mm[1].x, mm[2].x, mm[3].x);
        *(float4*)&sM[wofs + 8 * ld + 4] = make_float4(mm[0].y, mm[1].y, mm[2].y, mm[3].y);
        __syncwarp();
        u64 a00 = dup2(b2v.x), a01 = dup2(b2v.x), a10 = dup2(b2v.y), a11 = dup2(b2v.y);
#pragma unroll
        for (int k = 0; k < 64; k++) {
            float2 wv = W2f[k * 32 + ld];
            const float2* pm = (const float2*)&sM[wofs + k * 4];
            u64 m01 = f2u(pm[0]), m23 = f2u(pm[1]);
            u64 w0 = dup2(wv.x), w1 = dup2(wv.y);
            a00 = ffma2(m01, w0, a00); a01 = ffma2(m23, w0, a01);
            a10 = ffma2(m01, w1, a10); a11 = ffma2(m23, w1, a11);
        }
        float2 A = upk(a00), B = upk(a01), C = upk(a10), D = upk(a11);
        float v0[4] = {A.x, A.y, B.x, B.y};
        float v1[4] = {C.x, C.y, D.x, D.y};
        float s[4], q[4];
#pragma unroll
        for (int i = 0; i < 4; i++) { s[i] = v0[i] + v1[i]; q[i] = v0[i] * v0[i] + v1[i] * v1[i]; }
#pragma unroll
        for (int o = 16; o; o >>= 1) {
#pragma unroll
            for (int i = 0; i < 4; i++) {
                s[i] += __shfl_xor_sync(~0u, s[i], o);
                q[i] += __shfl_xor_sync(~0u, q[i], o);
            }
        }
#pragma unroll
        for (int i = 0; i < 4; i++) {
            float m = s[i] * (1.f / 64.f);
            float rs = rsqrtf(q[i] * (1.f / 64.f) - m * m + EPS);
            float y0 = (v0[i] - m) * rs * gv.x + bev.x;
            float y1 = (v1[i] - m) * rs * gv.y + bev.y;
            red2(g_agg + (size_t)d[i] * 64 + c0, y0, y1);
        }
    }
}

// ---------------- node update: h += LN(silu([h,agg]@nW1+b1)@nW2+b2) ----------------
extern __shared__ float dsm[];
__global__ void __launch_bounds__(256) k_node_upd(
    const float* __restrict__ W1, const float* __restrict__ b1,
    const float* __restrict__ W2, const float* __restrict__ b2,
    const float* __restrict__ gam, const float* __restrict__ bet)
{
    float* sW1 = dsm;              // 128*64
    float* sW2 = sW1 + 8192;       // 64*64
    float* sb1 = sW2 + 4096;
    float* sb2 = sb1 + 64;
    float* sg  = sb2 + 64;
    float* sbe = sg + 64;
    float* sRow = sbe + 64;        // 8*128
    float* sU   = sRow + 1024;     // 8*64
    int tid = threadIdx.x;
    for (int i = tid; i < 8192; i += 256) sW1[i] = W1[i];
    for (int i = tid; i < 4096; i += 256) sW2[i] = W2[i];
    if (tid < 64) { sb1[tid] = b1[tid]; sb2[tid] = b2[tid]; sg[tid] = gam[tid]; sbe[tid] = bet[tid]; }
    __syncthreads();
    int w = tid >> 5, ld = tid & 31, c0 = 2 * ld;
    float2 b1v = ((float2*)sb1)[ld], b2v = ((float2*)sb2)[ld];
    float2 gv = ((float2*)sg)[ld], bev = ((float2*)sbe)[ld];
    const float2* W1f = (const float2*)sW1;
    const float2* W2f = (const float2*)sW2;
    float* row = sRow + w * 128;
    float* uu = sU + w * 64;
    int gwid = (blockIdx.x * 256 + tid) >> 5;
    int nw = (gridDim.x * 256) >> 5;
    for (int n = gwid; n < N_NODES; n += nw) {
        float2 hv = *(const float2*)(g_h + (size_t)n * 64 + c0);
        float2 av = *(const float2*)(g_agg + (size_t)n * 64 + c0);
        __syncwarp();
        *(float2*)(row + c0) = hv;
        *(float2*)(row + 64 + c0) = av;
        __syncwarp();
        u64 acc = pk2(b1v.x, b1v.y);
#pragma unroll
        for (int k = 0; k < 128; k++) acc = ffma2(dup2(row[k]), f2u(W1f[k * 32 + ld]), acc);
        float2 u = upk(acc); u.x = silu(u.x); u.y = silu(u.y);
        __syncwarp();
        *(float2*)(uu + c0) = u;
        __syncwarp();
        u64 acc2 = pk2(b2v.x, b2v.y);
#pragma unroll
        for (int k = 0; k < 64; k++) acc2 = ffma2(dup2(uu[k]), f2u(W2f[k * 32 + ld]), acc2);
        float2 v = upk(acc2);
        float s = v.x + v.y, q = v.x * v.x + v.y * v.y;
#pragma unroll
        for (int o = 16; o; o >>= 1) { s += __shfl_xor_sync(~0u, s, o); q += __shfl_xor_sync(~0u, q, o); }
        float m = s * (1.f / 64.f), rs = rsqrtf(q * (1.f / 64.f) - m * m + EPS);
        float2 out;
        out.x = hv.x + (v.x - m) * rs * gv.x + bev.x;
        out.y = hv.y + (v.y - m) * rs * gv.y + bev.y;
        *(float2*)(g_h + (size_t)n * 64 + c0) = out;
    }
}

__global__ void k_zero_pool() { int t = threadIdx.x; if (t < NG * 64) g_pool[t] = 0.f; }

// ---------------- local decoder + pooling scatter ----------------
__global__ void __launch_bounds__(256) k_decoder_local(
    const float* __restrict__ W1, const float* __restrict__ b1,
    const float* __restrict__ W2, const float* __restrict__ b2,
    const int* __restrict__ batch, float* __restrict__ out)
{
    __shared__ float sW1[4096], sW2[64 * 6], sb1[64], sb2_[8];
    __shared__ float sH[8][64], sU[8][64];
    int tid = threadIdx.x;
    for (int i = tid; i < 4096; i += 256) sW1[i] = W1[i];
    for (int i = tid; i < 384; i += 256) sW2[i] = W2[i];
    if (tid < 64) sb1[tid] = b1[tid];
    if (tid < 6) sb2_[tid] = b2[tid];
    __syncthreads();
    int w = tid >> 5, ld = tid & 31, c0 = 2 * ld;
    int n = blockIdx.x * 8 + w;
    if (n >= N_NODES) return;
    float2 hv = *(const float2*)(g_h + (size_t)n * 64 + c0);
    sH[w][c0] = hv.x; sH[w][c0 + 1] = hv.y;
    __syncwarp();
    const float2* W1f = (const float2*)sW1;
    u64 acc = pk2(sb1[c0], sb1[c0 + 1]);
#pragma unroll
    for (int k = 0; k < 64; k++) acc = ffma2(dup2(sH[w][k]), f2u(W1f[k * 32 + ld]), acc);
    float2 u = upk(acc); u.x = silu(u.x); u.y = silu(u.y);
    sU[w][c0] = u.x; sU[w][c0 + 1] = u.y;
    __syncwarp();
    if (ld < 6) {
        float o = sb2_[ld];
#pragma unroll
        for (int k = 0; k < 64; k++) o += sU[w][k] * sW2[k * 6 + ld];
        out[(size_t)n * 6 + ld] = o;
    }
    int g = __ldg(&batch[n]);
    red2(g_pool + g * 64 + c0, hv.x, hv.y);
}

// ---------------- global decoder (counts via binary search on sorted batch) ----------------
__global__ void k_global(const int* __restrict__ batch,
    const float* __restrict__ W1, const float* __restrict__ b1,
    const float* __restrict__ W2, const float* __restrict__ b2,
    float* __restrict__ out)
{
    __shared__ float sp[NG * 64];
    __shared__ float su[NG * 32];
    __shared__ int bnd[NG + 1];
    int t = threadIdx.x; // 128 threads
    if (t <= NG) {
        int lo = 0, hi = N_NODES;
        while (lo < hi) { int mid = (lo + hi) >> 1; if (batch[mid] < t) lo = mid + 1; else hi = mid; }
        bnd[t] = lo;
    }
    __syncthreads();
    for (int i = t; i < NG * 64; i += 128) {
        int g = i >> 6;
        float cnt = (float)(bnd[g + 1] - bnd[g]);
        sp[i] = g_pool[i] / fmaxf(cnt, 1.f);
    }
    __syncthreads();
    {
        int g = t >> 5, j = t & 31;
        float a = b1[j];
#pragma unroll
        for (int k = 0; k < 64; k++) a += sp[g * 64 + k] * W1[k * 32 + j];
        su[g * 32 + j] = silu(a);
    }
    __syncthreads();
    if (t < NG * 4) {
        int g = t >> 2, j = t & 3;
        float o = b2[j];
#pragma unroll
        for (int k = 0; k < 32; k++) o += su[g * 32 + k] * W2[k * 4 + j];
        out[(size_t)N_NODES * 6 + g * 4 + j] = o;
    }
}

extern "C" void kernel_launch(void* const* d_in, const int* in_sizes, int n_in,
                              void* d_out, int out_size) {
    (void)in_sizes; (void)n_in; (void)out_size;
    const float* x     = (const float*)d_in[0];
    const int*   ei    = (const int*)d_in[1];
    const float* eattr = (const float*)d_in[2];
    const int*   batch = (const int*)d_in[3];
    const float* casep = (const float*)d_in[4];
    const float* bcp   = (const float*)d_in[5];
    const float* encW1 = (const float*)d_in[6];  const float* encb1 = (const float*)d_in[7];
    const float* encW2 = (const float*)d_in[8];  const float* encb2 = (const float*)d_in[9];
    const float* encg  = (const float*)d_in[10]; const float* encbe = (const float*)d_in[11];
    const float* eW1   = (const float*)d_in[12]; const float* eb1   = (const float*)d_in[13];
    const float* eW2   = (const float*)d_in[14]; const float* eb2   = (const float*)d_in[15];
    const float* eg    = (const float*)d_in[16]; const float* ebe   = (const float*)d_in[17];
    const float* nW1   = (const float*)d_in[18]; const float* nb1   = (const float*)d_in[19];
    const float* nW2   = (const float*)d_in[20]; const float* nb2   = (const float*)d_in[21];
    const float* ngm   = (const float*)d_in[22]; const float* nbe   = (const float*)d_in[23];
    const float* dlW1  = (const float*)d_in[24]; const float* dlb1  = (const float*)d_in[25];
    const float* dlW2  = (const float*)d_in[26]; const float* dlb2  = (const float*)d_in[27];
    const float* dgW1  = (const float*)d_in[28]; const float* dgb1  = (const float*)d_in[29];
    const float* dgW2  = (const float*)d_in[30]; const float* dgb2  = (const float*)d_in[31];
    float* out = (float*)d_out;

    size_t updSmem = (size_t)(8192 + 4096 + 256 + 1024 + 512) * sizeof(float);
    cudaFuncSetAttribute(k_node_upd, cudaFuncAttributeMaxDynamicSharedMemorySize, (int)updSmem);

    k_encoder<<<(N_NODES + 7) / 8, 256>>>(x, batch, casep, bcp, encW1, encb1, encW2, encb2, encg, encbe);
    for (int l = 0; l < NL; l++) {
        const float* eW1l = eW1 + (size_t)l * 133 * 64;
        k_node_pre<<<(N_NODES + 7) / 8, 256>>>(eW1l);
        k_edge<<<1184, 256>>>(ei, eattr,
                              eW1l + 128 * 64, eb1 + l * 64,
                              eW2 + (size_t)l * 4096, eb2 + l * 64,
                              eg + l * 64, ebe + l * 64);
        k_node_upd<<<592, 256, updSmem>>>(nW1 + (size_t)l * 8192, nb1 + l * 64,
                                          nW2 + (size_t)l * 4096, nb2 + l * 64,
                                          ngm + l * 64, nbe + l * 64);
    }
    k_zero_pool<<<1, 256>>>();
    k_decoder_local<<<(N_NODES + 7) / 8, 256>>>(dlW1, dlb1, dlW2, dlb2, batch, out);
    k_global<<<1, 128>>>(batch, dgW1, dgb1, dgW2, dgb2, out);
}